// round 16
// baseline (speedup 1.0000x reference)
#include <cuda_runtime.h>
#include <cuda_bf16.h>
#include <cstdint>

typedef unsigned long long ULL;

// ---------------- scratch (static device allocations; no cudaMalloc) -------
__device__ float g_xproj[67108864];           // [2][16384][2048] fp32
__device__ __nv_bfloat16 g_hb[16777216];      // h bf16 [b*512+t][1024] (fwd|bwd)
__device__ float g_emis[16384 * 32];
__device__ float g_llh[32];
__device__ unsigned g_cnt[8];                 // [d][batch-group]
__device__ __nv_bfloat16 g_xb[16777216];      // X in bf16 [16384][1024]
__device__ __nv_bfloat16 g_wb[2][2097152];    // W_ih in bf16 [2][2048][1024]
__device__ __nv_bfloat16 g_wtb[32768];        // W_tag bf16 [32][1024]

// ---------------- helpers ---------------------------------------------------
__device__ __forceinline__ uint32_t smem_u32(const void* p) {
    uint32_t a;
    asm("{ .reg .u64 t; cvta.to.shared.u64 t, %1; cvt.u32.u64 %0, t; }" : "=r"(a) : "l"(p));
    return a;
}
__device__ __forceinline__ void cp16(uint32_t s, const void* g) {
    asm volatile("cp.async.cg.shared.global [%0], [%1], 16;" :: "r"(s), "l"(g));
}
#define CP_COMMIT() asm volatile("cp.async.commit_group;")
#define CP_WAIT(n)  asm volatile("cp.async.wait_group %0;" :: "n"(n))
#define LDSM_X4(r0, r1, r2, r3, addr) \
    asm volatile("ldmatrix.sync.aligned.m8n8.x4.shared.b16 {%0,%1,%2,%3}, [%4];" \
                 : "=r"(r0), "=r"(r1), "=r"(r2), "=r"(r3) : "r"(addr))
#define LDSM_X2(r0, r1, addr) \
    asm volatile("ldmatrix.sync.aligned.m8n8.x2.shared.b16 {%0,%1}, [%2];" \
                 : "=r"(r0), "=r"(r1) : "r"(addr))
#define MMA_BF16(c0, c1, c2, c3, a0, a1, a2, a3, b0, b1) \
    asm volatile("mma.sync.aligned.m16n8k16.row.col.f32.bf16.bf16.f32 " \
                 "{%0,%1,%2,%3}, {%4,%5,%6,%7}, {%8,%9}, {%0,%1,%2,%3};" \
                 : "+f"(c0), "+f"(c1), "+f"(c2), "+f"(c3) \
                 : "r"(a0), "r"(a1), "r"(a2), "r"(a3), "r"(b0), "r"(b1))

__device__ __forceinline__ uint4 pack8_bf16(const float* s) {
    __nv_bfloat162 p[4];
#pragma unroll
    for (int i = 0; i < 4; i++) {
        p[i].x = __float2bfloat16_rn(s[2 * i]);
        p[i].y = __float2bfloat16_rn(s[2 * i + 1]);
    }
    return *(uint4*)p;
}

// ---------------- 0) fp32 -> bf16 conversion prepass -------------------------
__global__ __launch_bounds__(256) void cvt_x_kernel(const float* __restrict__ x) {
    if (blockIdx.x == 0 && threadIdx.x < 8) g_cnt[threadIdx.x] = 0u;
    int i8 = (blockIdx.x * 256 + threadIdx.x) * 8;
    float v[8];
    *(float4*)v = *(const float4*)(x + i8);
    *(float4*)(v + 4) = *(const float4*)(x + i8 + 4);
    *(uint4*)(g_xb + i8) = pack8_bf16(v);
}
__global__ __launch_bounds__(256) void cvt_w_kernel(const float* __restrict__ wf,
                                                    const float* __restrict__ wb) {
    const float* w = blockIdx.y ? wb : wf;
    __nv_bfloat16* o = g_wb[blockIdx.y];
    int i8 = (blockIdx.x * 256 + threadIdx.x) * 8;
    float v[8];
    *(float4*)v = *(const float4*)(w + i8);
    *(float4*)(v + 4) = *(const float4*)(w + i8 + 4);
    *(uint4*)(o + i8) = pack8_bf16(v);
}
__global__ __launch_bounds__(256) void cvt_wt_kernel(const float* __restrict__ wt) {
    int i8 = (blockIdx.x * 256 + threadIdx.x) * 8;
    float v[8];
    *(float4*)v = *(const float4*)(wt + i8);
    *(float4*)(v + 4) = *(const float4*)(wt + i8 + 4);
    *(uint4*)(g_wtb + i8) = pack8_bf16(v);
}

// ---------------- 1) input projection via HMMA mma.sync bf16 -----------------
#define PROJ_SMEM 65536

__global__ __launch_bounds__(256) void proj_hmma_kernel(
    const float* __restrict__ bf, const float* __restrict__ bb)
{
    extern __shared__ __align__(16) char psm[];
    const uint32_t sbase = smem_u32(psm);

    const int tid = threadIdx.x;
    const int wid = tid >> 5;
    const int lane = tid & 31;
    const int d = blockIdx.z;
    const int n0 = blockIdx.x * 128;
    const int m0 = blockIdx.y * 128;
    const __nv_bfloat16* Wb16 = g_wb[d];
    const float* bias = d ? bb : bf;
    float* C = g_xproj + (size_t)d * (16384ull * 2048ull);

    const int wm = wid >> 2;
    const int wn = wid & 3;

    float c[4][4][4];
#pragma unroll
    for (int mi = 0; mi < 4; mi++)
#pragma unroll
        for (int ni = 0; ni < 4; ni++)
#pragma unroll
            for (int q = 0; q < 4; q++) c[mi][ni][q] = 0.f;

#define STAGE(kc, buf) do { \
    _Pragma("unroll") \
    for (int i = 0; i < 4; i++) { \
        int u = tid + 256 * i; \
        int row = u >> 3, un = u & 7; \
        uint32_t sw = (uint32_t)((un ^ (row & 7)) * 16); \
        cp16(sbase + (buf) * 32768 + row * 128 + sw, \
             g_xb + (size_t)(m0 + row) * 1024 + (kc) * 64 + un * 8); \
        cp16(sbase + (buf) * 32768 + 16384 + row * 128 + sw, \
             Wb16 + (size_t)(n0 + row) * 1024 + (kc) * 64 + un * 8); \
    } \
    CP_COMMIT(); \
} while (0)

    STAGE(0, 0);
    for (int kc = 0; kc < 16; kc++) {
        const int buf = kc & 1;
        if (kc < 15) { STAGE(kc + 1, buf ^ 1); CP_WAIT(1); }
        else         { CP_WAIT(0); }
        __syncthreads();

        const uint32_t abase = sbase + buf * 32768;
        const uint32_t bbase = abase + 16384;
#pragma unroll
        for (int k16 = 0; k16 < 4; k16++) {
            uint32_t a[4][4];
#pragma unroll
            for (int mi = 0; mi < 4; mi++) {
                int row = wm * 64 + mi * 16 + (lane & 15);
                int un = k16 * 2 + (lane >> 4);
                uint32_t addr = abase + row * 128 + ((un ^ (row & 7)) * 16);
                LDSM_X4(a[mi][0], a[mi][1], a[mi][2], a[mi][3], addr);
            }
            uint32_t b[4][2];
#pragma unroll
            for (int ni = 0; ni < 4; ni++) {
                int row = wn * 32 + ni * 8 + (lane & 7);
                int un = k16 * 2 + ((lane >> 3) & 1);
                uint32_t addr = bbase + row * 128 + ((un ^ (row & 7)) * 16);
                LDSM_X2(b[ni][0], b[ni][1], addr);
            }
#pragma unroll
            for (int mi = 0; mi < 4; mi++)
#pragma unroll
                for (int ni = 0; ni < 4; ni++)
                    MMA_BF16(c[mi][ni][0], c[mi][ni][1], c[mi][ni][2], c[mi][ni][3],
                             a[mi][0], a[mi][1], a[mi][2], a[mi][3],
                             b[ni][0], b[ni][1]);
        }
        __syncthreads();
    }
#undef STAGE

#pragma unroll
    for (int ni = 0; ni < 4; ni++) {
        const int n = n0 + wn * 32 + ni * 8 + (lane & 3) * 2;
        const float bx = bias[n], by = bias[n + 1];
#pragma unroll
        for (int mi = 0; mi < 4; mi++) {
            const int m = m0 + wm * 64 + mi * 16 + (lane >> 2);
            float2 v0 = make_float2(c[mi][ni][0] + bx, c[mi][ni][1] + by);
            float2 v1 = make_float2(c[mi][ni][2] + bx, c[mi][ni][3] + by);
            *(float2*)(C + (size_t)m * 2048 + n) = v0;
            *(float2*)(C + (size_t)(m + 8) * 2048 + n) = v1;
        }
    }
}

// ---------------- 2) persistent BiLSTM recurrence, warp-autonomous -----------
// 128 CTAs = d(2) x bg(4) x hg(16). Per CTA-step: gates[128r x 8b] via HMMA.
// Per-warp spin + warp-private 1KB h restage + double-buffered partials:
// exactly ONE __syncthreads per step. Release: one red.release per warp,
// counter target 256*s (16 CTAs x 16 warps per (d,bg)).
#define PSLAB 1312                     /* floats per k-slab */
#define HS_B  0                        /* 16 warp-private 1KB regions */
#define PART_B 16384
#define PBUF_BYTES (8 * PSLAB * 4)     /* 41984 */
#define PERSIST_SMEM 131072            /* A staging needs 128KB at init */

__global__ __launch_bounds__(512, 1) void lstm_persist_hmma_kernel(
    const float* __restrict__ whf, const float* __restrict__ whb)
{
    extern __shared__ __align__(16) char smc[];
    const uint32_t sbase = smem_u32(smc);
    const uint32_t ast_base = sbase;            // A staging aliases everything

    const int blk = blockIdx.x;
    const int d = blk >> 6;
    const int bg = (blk >> 4) & 3;
    const int hg = blk & 15;
    const int tid = threadIdx.x;
    const int warp = tid >> 5;
    const int lane = tid & 31;
    const float* w = d ? whb : whf;

    // ---- stage W_hh slice (128 rows x 512 k, fp32->bf16, swizzled) ----------
#pragma unroll
    for (int it = 0; it < 16; it++) {
        int gi = tid + 512 * it;                // 0..8191 granules
        int r = gi >> 6;                        // 0..127 local gate row
        int g = gi & 63;
        int grow = 512 * (r >> 5) + hg * 32 + (r & 31);
        float v[8];
        *(float4*)v = *(const float4*)(w + (size_t)grow * 512 + g * 8);
        *(float4*)(v + 4) = *(const float4*)(w + (size_t)grow * 512 + g * 8 + 4);
        *(uint4*)(smc + r * 1024 + ((g ^ (r & 7)) * 16)) = pack8_bf16(v);
    }
    __syncthreads();

    const int ks = warp >> 1;                   // k-split 0..7 (k = ks*64)
    const int rh = warp & 1;                    // row half (64 rows)
    uint32_t afr[4][4][4];                      // [mi][kt][4] = 64 regs
    {
        const int q = lane >> 3;
#pragma unroll
        for (int mi = 0; mi < 4; mi++)
#pragma unroll
            for (int kt = 0; kt < 4; kt++) {
                int r = rh * 64 + mi * 16 + (q & 1) * 8 + (lane & 7);
                int g = ks * 8 + kt * 2 + (q >> 1);
                uint32_t addr = ast_base + r * 1024 + ((g ^ (r & 7)) * 16);
                LDSM_X4(afr[mi][kt][0], afr[mi][kt][1], afr[mi][kt][2], afr[mi][kt][3], addr);
            }
    }
    __syncthreads();                            // smem now reusable for hs/part

    // ---- warp-private h region + fixed B ldmatrix addresses -----------------
    const uint32_t wreg = (uint32_t)(HS_B + warp * 1024);
    uint32_t baddr[4];
    {
        const int l8 = lane & 7;
        const int lh = (lane >> 3) & 1;
#pragma unroll
        for (int kt = 0; kt < 4; kt++) {
            int gl = kt * 2 + lh;               // local granule 0..7
            baddr[kt] = sbase + wreg + l8 * 128 + ((gl ^ l8) * 16);
        }
    }
    // restage roles: lane -> (batch row rb, 2 granules of 16 units)
    const int rb = lane >> 2;                   // 0..7
    const int gsub = lane & 3;                  // granule pair 0..3
    const uint32_t rs_d0 = wreg + rb * 128 + (((gsub * 2) ^ rb) * 16);
    const uint32_t rs_d1 = wreg + rb * 128 + (((gsub * 2 + 1) ^ rb) * 16);

    // ---- reduce/cell roles: paired lanes (lane, lane^16) own one (u,b) ------
    const int pair = warp * 16 + (lane & 15);   // 0..255
    const int u = pair & 31;
    const int bb = pair >> 5;                   // 0..7 local batch
    const int half = lane >> 4;                 // 0: gates i,f  1: g,o
    const int qA = half * 2, qB = half * 2 + 1;
    const int lrA = qA * 32 + u, lrB = qB * 32 + u;
    const int growA = 512 * qA + hg * 32 + u;
    const int growB = 512 * qB + hg * 32 + u;
    const int gbatch = bg * 8 + bb;
    const int oA = bb * 164 + lrA + ((lrA >> 5) << 3);
    const int oB = bb * 164 + lrB + ((lrB >> 5) << 3);
    const float* xp = g_xproj + (size_t)d * (16384ull * 2048ull);

    float c_reg = 0.f;                          // owned by half==0 threads
    const int crow = lane >> 2;
    const int ccol = (lane & 3) * 2;

    unsigned* cntp = &g_cnt[d * 4 + bg];

    for (int s = 0; s < 512; s++) {
        const int t = d ? (511 - s) : s;
        float* part = (float*)(smc + PART_B + (s & 1) * PBUF_BYTES);

        // prefetch xproj (DRAM) before the spin
        float pfA = xp[((size_t)gbatch * 512 + t) * 2048 + growA];
        float pfB = xp[((size_t)gbatch * 512 + t) * 2048 + growB];

        if (s > 0) {
            if (lane == 0) {
                const unsigned target = 256u * (unsigned)s;
                unsigned v;
                do {
                    asm volatile("ld.acquire.gpu.u32 %0, [%1];" : "=r"(v) : "l"(cntp) : "memory");
                } while (v < target);
            }
            __syncwarp();
            // warp-private restage: 8 batches x 64 units (this warp's k-range)
            const int tp = d ? (512 - s) : (s - 1);
            const __nv_bfloat16* src = g_hb + ((size_t)(bg * 8 + rb) * 512 + tp) * 1024
                                       + d * 512 + ks * 64 + gsub * 16;
            uint4 v0 = __ldcg((const uint4*)src);
            uint4 v1 = __ldcg((const uint4*)(src + 8));
            *(uint4*)(smc + rs_d0) = v0;
            *(uint4*)(smc + rs_d1) = v1;
            __syncwarp();
        } else {
            *(uint4*)(smc + rs_d0) = make_uint4(0u, 0u, 0u, 0u);
            *(uint4*)(smc + rs_d1) = make_uint4(0u, 0u, 0u, 0u);
            __syncwarp();
        }

        // ---- tensor GEMM: c = Whh_slice @ h (warp-private B) ----------------
        {
            uint32_t bfr[4][2];
#pragma unroll
            for (int kt = 0; kt < 4; kt++)
                LDSM_X2(bfr[kt][0], bfr[kt][1], baddr[kt]);

            float c[4][4];
#pragma unroll
            for (int mi = 0; mi < 4; mi++)
#pragma unroll
                for (int q = 0; q < 4; q++) c[mi][q] = 0.f;

#pragma unroll
            for (int mi = 0; mi < 4; mi++)
#pragma unroll
                for (int kt = 0; kt < 4; kt++)
                    MMA_BF16(c[mi][0], c[mi][1], c[mi][2], c[mi][3],
                             afr[mi][kt][0], afr[mi][kt][1], afr[mi][kt][2], afr[mi][kt][3],
                             bfr[kt][0], bfr[kt][1]);

            float* pw = part + ks * PSLAB;
#pragma unroll
            for (int mi = 0; mi < 4; mi++) {
                const int rbase = rh * 64 + mi * 16;
                const int skew = (rbase >> 5) << 3;
                const int r = rbase + crow + skew;
                pw[ccol * 164 + r] = c[mi][0];
                pw[(ccol + 1) * 164 + r] = c[mi][1];
                pw[ccol * 164 + r + 8] = c[mi][2];
                pw[(ccol + 1) * 164 + r + 8] = c[mi][3];
            }
        }
        __syncthreads();                        // the ONE CTA barrier per step

        // ---- reduce 8 k-slabs + cell update ---------------------------------
        {
            float vA = pfA, vB = pfB;
#pragma unroll
            for (int kk = 0; kk < 8; kk++) {
                vA += part[kk * PSLAB + oA];
                vB += part[kk * PSLAB + oB];
            }
            float xg = __shfl_xor_sync(0xffffffffu, vA, 16);
            float xo = __shfl_xor_sync(0xffffffffu, vB, 16);
            if (half == 0) {
                float si = 1.f / (1.f + __expf(-vA));
                float sf = 1.f / (1.f + __expf(-vB));
                float so = 1.f / (1.f + __expf(-xo));
                float tg = tanhf(xg);
                c_reg = sf * c_reg + si * tg;
                float hv = so * tanhf(c_reg);
                g_hb[((size_t)gbatch * 512 + t) * 1024 + d * 512 + hg * 32 + u] =
                    __float2bfloat16_rn(hv);
            }
        }

        // ---- per-warp release (orders this warp's h stores) -----------------
        __syncwarp();
        if (lane == 0)
            asm volatile("red.release.gpu.add.u32 [%0], %1;" :: "l"(cntp), "r"(1u) : "memory");
    }
}

// ---------------- 3) LayerNorm + emissions (bf16 h, bf16 W_tag) --------------
__global__ __launch_bounds__(256) void ln_emis_kernel(
    const float* __restrict__ lng, const float* __restrict__ lnb,
    const float* __restrict__ bt)
{
    __shared__ float shn[1024];
    __shared__ float red[16];
    const int row = blockIdx.x;
    const int tid = threadIdx.x;
    const __nv_bfloat16* hp = g_hb + (size_t)row * 1024;
    __nv_bfloat162 hv2[2];
    *(uint2*)hv2 = *(const uint2*)(hp + tid * 4);
    float vx = __bfloat162float(hv2[0].x), vy = __bfloat162float(hv2[0].y);
    float vz = __bfloat162float(hv2[1].x), vw = __bfloat162float(hv2[1].y);
    float s1 = vx + vy + vz + vw;
    float s2 = vx * vx + vy * vy + vz * vz + vw * vw;
#pragma unroll
    for (int o = 16; o; o >>= 1) {
        s1 += __shfl_down_sync(0xffffffffu, s1, o);
        s2 += __shfl_down_sync(0xffffffffu, s2, o);
    }
    const int w = tid >> 5, ln = tid & 31;
    if (ln == 0) { red[w] = s1; red[8 + w] = s2; }
    __syncthreads();
    if (tid == 0) {
        float a = 0.f, bq = 0.f;
#pragma unroll
        for (int i = 0; i < 8; i++) { a += red[i]; bq += red[8 + i]; }
        float mu = a * (1.f / 1024.f);
        float var = bq * (1.f / 1024.f) - mu * mu;
        red[0] = mu;
        red[1] = rsqrtf(var + 1e-5f);
    }
    __syncthreads();
    const float mu = red[0], rs = red[1];
    float4 g4 = *(const float4*)(lng + tid * 4);
    float4 b4 = *(const float4*)(lnb + tid * 4);
    shn[tid * 4 + 0] = (vx - mu) * rs * g4.x + b4.x;
    shn[tid * 4 + 1] = (vy - mu) * rs * g4.y + b4.y;
    shn[tid * 4 + 2] = (vz - mu) * rs * g4.z + b4.z;
    shn[tid * 4 + 3] = (vw - mu) * rs * g4.w + b4.w;
    __syncthreads();
#pragma unroll
    for (int tt = 0; tt < 4; tt++) {
        const int tag = w * 4 + tt;
        const __nv_bfloat16* wrow = g_wtb + (size_t)tag * 1024;
        float acc = 0.f;
#pragma unroll
        for (int i = 0; i < 32; i++)
            acc += shn[ln + 32 * i] * __bfloat162float(wrow[ln + 32 * i]);
#pragma unroll
        for (int o = 16; o; o >>= 1) acc += __shfl_down_sync(0xffffffffu, acc, o);
        if (ln == 0) g_emis[(size_t)row * 32 + tag] = acc + bt[tag];
    }
}

// ---------------- 4) CRF log-likelihood (one warp per batch) -----------------
__global__ void crf_kernel(const int* __restrict__ tags,
                           const int* __restrict__ mask,
                           const float* __restrict__ trans,
                           const float* __restrict__ st,
                           const float* __restrict__ en)
{
    __shared__ float tr[32 * 33];
    const int b = blockIdx.x;
    const int jx = threadIdx.x;
    for (int i = jx; i < 1024; i += 32) tr[(i >> 5) * 33 + (i & 31)] = trans[i];
    __syncwarp();
    const float* eb = g_emis + (size_t)b * 512 * 32;
    const int* tg = tags + (size_t)b * 512;
    const int* mk = mask + (size_t)b * 512;

    float alpha = st[jx] + eb[jx];
    float np = 0.f;
    int ms = 0;
    for (int l = jx; l < 512; l += 32) {
        int m = mk[l];
        ms += m;
        if (l > 0 && m) {
            int tp = tg[l - 1], tc = tg[l];
            np += tr[tp * 33 + tc] + eb[l * 32 + tc];
        }
    }
    if (jx == 0) np += st[tg[0]] + eb[tg[0]];
#pragma unroll
    for (int o = 16; o; o >>= 1) {
        np += __shfl_xor_sync(0xffffffffu, np, o);
        ms += __shfl_xor_sync(0xffffffffu, ms, o);
    }
    const int lastidx = ms - 1;
    const float nend = en[tg[lastidx]];

    for (int l = 1; l < 512; l++) {
        float v[32];
        float mx = -1e30f;
#pragma unroll
        for (int i = 0; i < 32; i++) {
            float ai = __shfl_sync(0xffffffffu, alpha, i);
            v[i] = ai + tr[i * 33 + jx];
            mx = fmaxf(mx, v[i]);
        }
        float sa = 0.f;
#pragma unroll
        for (int i = 0; i < 32; i++) sa += __expf(v[i] - mx);
        float anew = mx + __logf(sa) + eb[l * 32 + jx];
        alpha = mk[l] ? anew : alpha;
    }
    float z = alpha + en[jx];
    float mz = z;
#pragma unroll
    for (int o = 16; o; o >>= 1) mz = fmaxf(mz, __shfl_xor_sync(0xffffffffu, mz, o));
    float sz = __expf(z - mz);
#pragma unroll
    for (int o = 16; o; o >>= 1) sz += __shfl_xor_sync(0xffffffffu, sz, o);
    float logZ = mz + __logf(sz);
    if (jx == 0) g_llh[b] = np + nend - logZ;
}

// ---------------- 5) final reduce --------------------------------------------
__global__ void final_kernel(float* out) {
    float v = g_llh[threadIdx.x];
#pragma unroll
    for (int o = 16; o; o >>= 1) v += __shfl_xor_sync(0xffffffffu, v, o);
    if (threadIdx.x == 0) out[0] = -v * (1.f / 32.f);
}

// ---------------- launch ------------------------------------------------------
extern "C" void kernel_launch(void* const* d_in, const int* in_sizes, int n_in,
                              void* d_out, int out_size) {
    const float* x     = (const float*)d_in[0];
    const int*   tags  = (const int*)d_in[1];   // int32 (JAX x64 disabled)
    const int*   mask  = (const int*)d_in[2];
    const float* wihf  = (const float*)d_in[3];
    const float* whhf  = (const float*)d_in[4];
    const float* bf    = (const float*)d_in[5];
    const float* wihb  = (const float*)d_in[6];
    const float* whhb  = (const float*)d_in[7];
    const float* bb    = (const float*)d_in[8];
    const float* lng   = (const float*)d_in[9];
    const float* lnb   = (const float*)d_in[10];
    const float* Wt    = (const float*)d_in[11];
    const float* bt    = (const float*)d_in[12];
    const float* trans = (const float*)d_in[13];
    const float* st    = (const float*)d_in[14];
    const float* en    = (const float*)d_in[15];
    float* out = (float*)d_out;

    cudaFuncSetAttribute(lstm_persist_hmma_kernel,
                         cudaFuncAttributeMaxDynamicSharedMemorySize, PERSIST_SMEM);
    cudaFuncSetAttribute(proj_hmma_kernel,
                         cudaFuncAttributeMaxDynamicSharedMemorySize, PROJ_SMEM);

    cvt_x_kernel<<<8192, 256>>>(x);
    cvt_w_kernel<<<dim3(1024, 2), 256>>>(wihf, wihb);
    cvt_wt_kernel<<<16, 256>>>(Wt);
    proj_hmma_kernel<<<dim3(16, 128, 2), 256, PROJ_SMEM>>>(bf, bb);
    lstm_persist_hmma_kernel<<<128, 512, PERSIST_SMEM>>>(whhf, whhb);
    ln_emis_kernel<<<16384, 256>>>(lng, lnb, bt);
    crf_kernel<<<32, 32>>>(tags, mask, trans, st, en);
    final_kernel<<<1, 32>>>(out);
    (void)in_sizes; (void)n_in; (void)out_size;
}

// round 17
// speedup vs baseline: 1.8581x; 1.8581x over previous
#include <cuda_runtime.h>
#include <cuda_bf16.h>
#include <cstdint>

typedef unsigned long long ULL;

// ---------------- scratch (static device allocations; no cudaMalloc) -------
__device__ float g_xproj[67108864];           // [2][16384][2048] fp32
__device__ __nv_bfloat16 g_hb[16777216];      // h bf16 [b*512+t][1024] (fwd|bwd)
__device__ float g_emis[16384 * 32];
__device__ float g_llh[32];
__device__ unsigned g_cnt[8];                 // [d][batch-group]
__device__ __nv_bfloat16 g_xb[16777216];      // X in bf16 [16384][1024]
__device__ __nv_bfloat16 g_wb[2][2097152];    // W_ih in bf16 [2][2048][1024]
__device__ __nv_bfloat16 g_wtb[32768];        // W_tag bf16 [32][1024]

// ---------------- helpers ---------------------------------------------------
__device__ __forceinline__ uint32_t smem_u32(const void* p) {
    uint32_t a;
    asm("{ .reg .u64 t; cvta.to.shared.u64 t, %1; cvt.u32.u64 %0, t; }" : "=r"(a) : "l"(p));
    return a;
}
__device__ __forceinline__ void cp16(uint32_t s, const void* g) {
    asm volatile("cp.async.cg.shared.global [%0], [%1], 16;" :: "r"(s), "l"(g));
}
#define CP_COMMIT() asm volatile("cp.async.commit_group;")
#define CP_WAIT(n)  asm volatile("cp.async.wait_group %0;" :: "n"(n))
#define LDSM_X4(r0, r1, r2, r3, addr) \
    asm volatile("ldmatrix.sync.aligned.m8n8.x4.shared.b16 {%0,%1,%2,%3}, [%4];" \
                 : "=r"(r0), "=r"(r1), "=r"(r2), "=r"(r3) : "r"(addr))
#define LDSM_X2(r0, r1, addr) \
    asm volatile("ldmatrix.sync.aligned.m8n8.x2.shared.b16 {%0,%1}, [%2];" \
                 : "=r"(r0), "=r"(r1) : "r"(addr))
#define MMA_BF16(c0, c1, c2, c3, a0, a1, a2, a3, b0, b1) \
    asm volatile("mma.sync.aligned.m16n8k16.row.col.f32.bf16.bf16.f32 " \
                 "{%0,%1,%2,%3}, {%4,%5,%6,%7}, {%8,%9}, {%0,%1,%2,%3};" \
                 : "+f"(c0), "+f"(c1), "+f"(c2), "+f"(c3) \
                 : "r"(a0), "r"(a1), "r"(a2), "r"(a3), "r"(b0), "r"(b1))

__device__ __forceinline__ uint4 pack8_bf16(const float* s) {
    __nv_bfloat162 p[4];
#pragma unroll
    for (int i = 0; i < 4; i++) {
        p[i].x = __float2bfloat16_rn(s[2 * i]);
        p[i].y = __float2bfloat16_rn(s[2 * i + 1]);
    }
    return *(uint4*)p;
}

// ---------------- 0) fp32 -> bf16 conversion prepass -------------------------
__global__ __launch_bounds__(256) void cvt_x_kernel(const float* __restrict__ x) {
    if (blockIdx.x == 0 && threadIdx.x < 8) g_cnt[threadIdx.x] = 0u;
    int i8 = (blockIdx.x * 256 + threadIdx.x) * 8;
    float v[8];
    *(float4*)v = *(const float4*)(x + i8);
    *(float4*)(v + 4) = *(const float4*)(x + i8 + 4);
    *(uint4*)(g_xb + i8) = pack8_bf16(v);
}
__global__ __launch_bounds__(256) void cvt_w_kernel(const float* __restrict__ wf,
                                                    const float* __restrict__ wb) {
    const float* w = blockIdx.y ? wb : wf;
    __nv_bfloat16* o = g_wb[blockIdx.y];
    int i8 = (blockIdx.x * 256 + threadIdx.x) * 8;
    float v[8];
    *(float4*)v = *(const float4*)(w + i8);
    *(float4*)(v + 4) = *(const float4*)(w + i8 + 4);
    *(uint4*)(o + i8) = pack8_bf16(v);
}
__global__ __launch_bounds__(256) void cvt_wt_kernel(const float* __restrict__ wt) {
    int i8 = (blockIdx.x * 256 + threadIdx.x) * 8;
    float v[8];
    *(float4*)v = *(const float4*)(wt + i8);
    *(float4*)(v + 4) = *(const float4*)(wt + i8 + 4);
    *(uint4*)(g_wtb + i8) = pack8_bf16(v);
}

// ---------------- 1) input projection via HMMA mma.sync bf16 -----------------
#define PROJ_SMEM 65536

__global__ __launch_bounds__(256) void proj_hmma_kernel(
    const float* __restrict__ bf, const float* __restrict__ bb)
{
    extern __shared__ __align__(16) char psm[];
    const uint32_t sbase = smem_u32(psm);

    const int tid = threadIdx.x;
    const int wid = tid >> 5;
    const int lane = tid & 31;
    const int d = blockIdx.z;
    const int n0 = blockIdx.x * 128;
    const int m0 = blockIdx.y * 128;
    const __nv_bfloat16* Wb16 = g_wb[d];
    const float* bias = d ? bb : bf;
    float* C = g_xproj + (size_t)d * (16384ull * 2048ull);

    const int wm = wid >> 2;
    const int wn = wid & 3;

    float c[4][4][4];
#pragma unroll
    for (int mi = 0; mi < 4; mi++)
#pragma unroll
        for (int ni = 0; ni < 4; ni++)
#pragma unroll
            for (int q = 0; q < 4; q++) c[mi][ni][q] = 0.f;

#define STAGE(kc, buf) do { \
    _Pragma("unroll") \
    for (int i = 0; i < 4; i++) { \
        int u = tid + 256 * i; \
        int row = u >> 3, un = u & 7; \
        uint32_t sw = (uint32_t)((un ^ (row & 7)) * 16); \
        cp16(sbase + (buf) * 32768 + row * 128 + sw, \
             g_xb + (size_t)(m0 + row) * 1024 + (kc) * 64 + un * 8); \
        cp16(sbase + (buf) * 32768 + 16384 + row * 128 + sw, \
             Wb16 + (size_t)(n0 + row) * 1024 + (kc) * 64 + un * 8); \
    } \
    CP_COMMIT(); \
} while (0)

    STAGE(0, 0);
    for (int kc = 0; kc < 16; kc++) {
        const int buf = kc & 1;
        if (kc < 15) { STAGE(kc + 1, buf ^ 1); CP_WAIT(1); }
        else         { CP_WAIT(0); }
        __syncthreads();

        const uint32_t abase = sbase + buf * 32768;
        const uint32_t bbase = abase + 16384;
#pragma unroll
        for (int k16 = 0; k16 < 4; k16++) {
            uint32_t a[4][4];
#pragma unroll
            for (int mi = 0; mi < 4; mi++) {
                int row = wm * 64 + mi * 16 + (lane & 15);
                int un = k16 * 2 + (lane >> 4);
                uint32_t addr = abase + row * 128 + ((un ^ (row & 7)) * 16);
                LDSM_X4(a[mi][0], a[mi][1], a[mi][2], a[mi][3], addr);
            }
            uint32_t b[4][2];
#pragma unroll
            for (int ni = 0; ni < 4; ni++) {
                int row = wn * 32 + ni * 8 + (lane & 7);
                int un = k16 * 2 + ((lane >> 3) & 1);
                uint32_t addr = bbase + row * 128 + ((un ^ (row & 7)) * 16);
                LDSM_X2(b[ni][0], b[ni][1], addr);
            }
#pragma unroll
            for (int mi = 0; mi < 4; mi++)
#pragma unroll
                for (int ni = 0; ni < 4; ni++)
                    MMA_BF16(c[mi][ni][0], c[mi][ni][1], c[mi][ni][2], c[mi][ni][3],
                             a[mi][0], a[mi][1], a[mi][2], a[mi][3],
                             b[ni][0], b[ni][1]);
        }
        __syncthreads();
    }
#undef STAGE

#pragma unroll
    for (int ni = 0; ni < 4; ni++) {
        const int n = n0 + wn * 32 + ni * 8 + (lane & 3) * 2;
        const float bx = bias[n], by = bias[n + 1];
#pragma unroll
        for (int mi = 0; mi < 4; mi++) {
            const int m = m0 + wm * 64 + mi * 16 + (lane >> 2);
            float2 v0 = make_float2(c[mi][ni][0] + bx, c[mi][ni][1] + by);
            float2 v1 = make_float2(c[mi][ni][2] + bx, c[mi][ni][3] + by);
            *(float2*)(C + (size_t)m * 2048 + n) = v0;
            *(float2*)(C + (size_t)(m + 8) * 2048 + n) = v1;
        }
    }
}

// ---------------- 2) persistent BiLSTM recurrence ----------------------------
// 128 CTAs = d(2) x bg(4) x hg(16). Per CTA-step: gates[128r x 8b] via HMMA.
// Low-contention protocol (R15): per-(d,bg) counter, 16 CTA-level releases per
// step, ONE tid0 L2 spin per CTA. Fan-out via smem flag (LDS broadcast).
// Warp-private 1KB h restage (no CTA barrier before GEMM).
// Exactly TWO __syncthreads per step.
#define PSLAB 1312                     /* floats per k-slab */
#define HS_B  0                        /* 16 warp-private 1KB regions */
#define PART_B 16384                   /* single buffer, ends 58368 */
#define FLAG_B 58368
#define PERSIST_SMEM 131072            /* A staging needs 128KB at init */

__global__ __launch_bounds__(512, 1) void lstm_persist_hmma_kernel(
    const float* __restrict__ whf, const float* __restrict__ whb)
{
    extern __shared__ __align__(16) char smc[];
    const uint32_t sbase = smem_u32(smc);
    const uint32_t ast_base = sbase;            // A staging aliases everything
    const uint32_t flag_addr = sbase + FLAG_B;
    float* part = (float*)(smc + PART_B);

    const int blk = blockIdx.x;
    const int d = blk >> 6;
    const int bg = (blk >> 4) & 3;
    const int hg = blk & 15;
    const int tid = threadIdx.x;
    const int warp = tid >> 5;
    const int lane = tid & 31;
    const float* w = d ? whb : whf;

    // ---- stage W_hh slice (128 rows x 512 k, fp32->bf16, swizzled) ----------
#pragma unroll
    for (int it = 0; it < 16; it++) {
        int gi = tid + 512 * it;                // 0..8191 granules
        int r = gi >> 6;                        // 0..127 local gate row
        int g = gi & 63;
        int grow = 512 * (r >> 5) + hg * 32 + (r & 31);
        float v[8];
        *(float4*)v = *(const float4*)(w + (size_t)grow * 512 + g * 8);
        *(float4*)(v + 4) = *(const float4*)(w + (size_t)grow * 512 + g * 8 + 4);
        *(uint4*)(smc + r * 1024 + ((g ^ (r & 7)) * 16)) = pack8_bf16(v);
    }
    __syncthreads();

    const int ks = warp >> 1;                   // k-split 0..7 (k = ks*64)
    const int rh = warp & 1;                    // row half (64 rows)
    uint32_t afr[4][4][4];                      // [mi][kt][4] = 64 regs
    {
        const int q = lane >> 3;
#pragma unroll
        for (int mi = 0; mi < 4; mi++)
#pragma unroll
            for (int kt = 0; kt < 4; kt++) {
                int r = rh * 64 + mi * 16 + (q & 1) * 8 + (lane & 7);
                int g = ks * 8 + kt * 2 + (q >> 1);
                uint32_t addr = ast_base + r * 1024 + ((g ^ (r & 7)) * 16);
                LDSM_X4(afr[mi][kt][0], afr[mi][kt][1], afr[mi][kt][2], afr[mi][kt][3], addr);
            }
    }
    __syncthreads();                            // smem now reusable
    if (tid == 0) *(volatile unsigned*)(smc + FLAG_B) = 0u;  // step-0 barriers order this

    // ---- warp-private h region + fixed B ldmatrix addresses -----------------
    const uint32_t wreg = (uint32_t)(HS_B + warp * 1024);
    uint32_t baddr[4];
    {
        const int l8 = lane & 7;
        const int lh = (lane >> 3) & 1;
#pragma unroll
        for (int kt = 0; kt < 4; kt++) {
            int gl = kt * 2 + lh;               // local granule 0..7
            baddr[kt] = sbase + wreg + l8 * 128 + ((gl ^ l8) * 16);
        }
    }
    // restage roles: lane -> (batch row rb, 2 granules of 8 units each)
    const int rb = lane >> 2;                   // 0..7
    const int gsub = lane & 3;                  // granule pair 0..3
    const uint32_t rs_d0 = wreg + rb * 128 + (((gsub * 2) ^ rb) * 16);
    const uint32_t rs_d1 = wreg + rb * 128 + (((gsub * 2 + 1) ^ rb) * 16);

    // ---- reduce/cell roles: paired lanes (lane, lane^16) own one (u,b) ------
    const int pair = warp * 16 + (lane & 15);   // 0..255
    const int u = pair & 31;
    const int bb = pair >> 5;                   // 0..7 local batch
    const int half = lane >> 4;                 // 0: gates i,f  1: g,o
    const int qA = half * 2, qB = half * 2 + 1;
    const int lrA = qA * 32 + u, lrB = qB * 32 + u;
    const int growA = 512 * qA + hg * 32 + u;
    const int growB = 512 * qB + hg * 32 + u;
    const int gbatch = bg * 8 + bb;
    const int oA = bb * 164 + lrA + ((lrA >> 5) << 3);
    const int oB = bb * 164 + lrB + ((lrB >> 5) << 3);
    const float* xp = g_xproj + (size_t)d * (16384ull * 2048ull);

    float c_reg = 0.f;                          // owned by half==0 threads
    const int crow = lane >> 2;
    const int ccol = (lane & 3) * 2;

    unsigned* cntp = &g_cnt[d * 4 + bg];

    for (int s = 0; s < 512; s++) {
        const int t = d ? (511 - s) : s;

        // prefetch xproj (DRAM) before the spin
        float pfA = xp[((size_t)gbatch * 512 + t) * 2048 + growA];
        float pfB = xp[((size_t)gbatch * 512 + t) * 2048 + growB];

        if (s > 0) {
            // tid0: L2 acquire-spin, then release the smem flag for all warps
            if (tid == 0) {
                const unsigned target = 16u * (unsigned)s;
                unsigned v;
                do {
                    asm volatile("ld.acquire.gpu.u32 %0, [%1];" : "=r"(v) : "l"(cntp) : "memory");
                } while (v < target);
                asm volatile("st.release.cta.shared.u32 [%0], %1;"
                             :: "r"(flag_addr), "r"((unsigned)s) : "memory");
            }
            // all threads: acquire-spin on the smem flag (LDS broadcast)
            {
                unsigned fv;
                do {
                    asm volatile("ld.acquire.cta.shared.u32 %0, [%1];"
                                 : "=r"(fv) : "r"(flag_addr) : "memory");
                } while (fv < (unsigned)s);
            }
            // warp-private restage: 8 batches x 64 units (this warp's k-range)
            const int tp = d ? (512 - s) : (s - 1);
            const __nv_bfloat16* src = g_hb + ((size_t)(bg * 8 + rb) * 512 + tp) * 1024
                                       + d * 512 + ks * 64 + gsub * 16;
            uint4 v0 = __ldcg((const uint4*)src);
            uint4 v1 = __ldcg((const uint4*)(src + 8));
            *(uint4*)(smc + rs_d0) = v0;
            *(uint4*)(smc + rs_d1) = v1;
            __syncwarp();
        } else {
            *(uint4*)(smc + rs_d0) = make_uint4(0u, 0u, 0u, 0u);
            *(uint4*)(smc + rs_d1) = make_uint4(0u, 0u, 0u, 0u);
            __syncwarp();
        }

        // ---- tensor GEMM: c = Whh_slice @ h (warp-private B) ----------------
        {
            uint32_t bfr[4][2];
#pragma unroll
            for (int kt = 0; kt < 4; kt++)
                LDSM_X2(bfr[kt][0], bfr[kt][1], baddr[kt]);

            float c[4][4];
#pragma unroll
            for (int mi = 0; mi < 4; mi++)
#pragma unroll
                for (int q = 0; q < 4; q++) c[mi][q] = 0.f;

#pragma unroll
            for (int mi = 0; mi < 4; mi++)
#pragma unroll
                for (int kt = 0; kt < 4; kt++)
                    MMA_BF16(c[mi][0], c[mi][1], c[mi][2], c[mi][3],
                             afr[mi][kt][0], afr[mi][kt][1], afr[mi][kt][2], afr[mi][kt][3],
                             bfr[kt][0], bfr[kt][1]);

            float* pw = part + ks * PSLAB;
#pragma unroll
            for (int mi = 0; mi < 4; mi++) {
                const int rbase = rh * 64 + mi * 16;
                const int skew = (rbase >> 5) << 3;
                const int r = rbase + crow + skew;
                pw[ccol * 164 + r] = c[mi][0];
                pw[(ccol + 1) * 164 + r] = c[mi][1];
                pw[ccol * 164 + r + 8] = c[mi][2];
                pw[(ccol + 1) * 164 + r + 8] = c[mi][3];
            }
        }
        __syncthreads();                        // partials visible to reduce

        // ---- reduce 8 k-slabs + cell update ---------------------------------
        {
            float vA = pfA, vB = pfB;
#pragma unroll
            for (int kk = 0; kk < 8; kk++) {
                vA += part[kk * PSLAB + oA];
                vB += part[kk * PSLAB + oB];
            }
            float xg = __shfl_xor_sync(0xffffffffu, vA, 16);
            float xo = __shfl_xor_sync(0xffffffffu, vB, 16);
            if (half == 0) {
                float si = 1.f / (1.f + __expf(-vA));
                float sf = 1.f / (1.f + __expf(-vB));
                float so = 1.f / (1.f + __expf(-xo));
                float tg = tanhf(xg);
                c_reg = sf * c_reg + si * tg;
                float hv = so * tanhf(c_reg);
                g_hb[((size_t)gbatch * 512 + t) * 1024 + d * 512 + hg * 32 + u] =
                    __float2bfloat16_rn(hv);
            }
        }

        // ---- all h-stores done -> single CTA-level release ------------------
        __syncthreads();
        if (tid == 0)
            asm volatile("red.release.gpu.add.u32 [%0], %1;" :: "l"(cntp), "r"(1u) : "memory");
    }
}

// ---------------- 3) LayerNorm + emissions (bf16 h, bf16 W_tag) --------------
__global__ __launch_bounds__(256) void ln_emis_kernel(
    const float* __restrict__ lng, const float* __restrict__ lnb,
    const float* __restrict__ bt)
{
    __shared__ float shn[1024];
    __shared__ float red[16];
    const int row = blockIdx.x;
    const int tid = threadIdx.x;
    const __nv_bfloat16* hp = g_hb + (size_t)row * 1024;
    __nv_bfloat162 hv2[2];
    *(uint2*)hv2 = *(const uint2*)(hp + tid * 4);
    float vx = __bfloat162float(hv2[0].x), vy = __bfloat162float(hv2[0].y);
    float vz = __bfloat162float(hv2[1].x), vw = __bfloat162float(hv2[1].y);
    float s1 = vx + vy + vz + vw;
    float s2 = vx * vx + vy * vy + vz * vz + vw * vw;
#pragma unroll
    for (int o = 16; o; o >>= 1) {
        s1 += __shfl_down_sync(0xffffffffu, s1, o);
        s2 += __shfl_down_sync(0xffffffffu, s2, o);
    }
    const int w = tid >> 5, ln = tid & 31;
    if (ln == 0) { red[w] = s1; red[8 + w] = s2; }
    __syncthreads();
    if (tid == 0) {
        float a = 0.f, bq = 0.f;
#pragma unroll
        for (int i = 0; i < 8; i++) { a += red[i]; bq += red[8 + i]; }
        float mu = a * (1.f / 1024.f);
        float var = bq * (1.f / 1024.f) - mu * mu;
        red[0] = mu;
        red[1] = rsqrtf(var + 1e-5f);
    }
    __syncthreads();
    const float mu = red[0], rs = red[1];
    float4 g4 = *(const float4*)(lng + tid * 4);
    float4 b4 = *(const float4*)(lnb + tid * 4);
    shn[tid * 4 + 0] = (vx - mu) * rs * g4.x + b4.x;
    shn[tid * 4 + 1] = (vy - mu) * rs * g4.y + b4.y;
    shn[tid * 4 + 2] = (vz - mu) * rs * g4.z + b4.z;
    shn[tid * 4 + 3] = (vw - mu) * rs * g4.w + b4.w;
    __syncthreads();
#pragma unroll
    for (int tt = 0; tt < 4; tt++) {
        const int tag = w * 4 + tt;
        const __nv_bfloat16* wrow = g_wtb + (size_t)tag * 1024;
        float acc = 0.f;
#pragma unroll
        for (int i = 0; i < 32; i++)
            acc += shn[ln + 32 * i] * __bfloat162float(wrow[ln + 32 * i]);
#pragma unroll
        for (int o = 16; o; o >>= 1) acc += __shfl_down_sync(0xffffffffu, acc, o);
        if (ln == 0) g_emis[(size_t)row * 32 + tag] = acc + bt[tag];
    }
}

// ---------------- 4) CRF log-likelihood (one warp per batch) -----------------
__global__ void crf_kernel(const int* __restrict__ tags,
                           const int* __restrict__ mask,
                           const float* __restrict__ trans,
                           const float* __restrict__ st,
                           const float* __restrict__ en)
{
    __shared__ float tr[32 * 33];
    const int b = blockIdx.x;
    const int jx = threadIdx.x;
    for (int i = jx; i < 1024; i += 32) tr[(i >> 5) * 33 + (i & 31)] = trans[i];
    __syncwarp();
    const float* eb = g_emis + (size_t)b * 512 * 32;
    const int* tg = tags + (size_t)b * 512;
    const int* mk = mask + (size_t)b * 512;

    float alpha = st[jx] + eb[jx];
    float np = 0.f;
    int ms = 0;
    for (int l = jx; l < 512; l += 32) {
        int m = mk[l];
        ms += m;
        if (l > 0 && m) {
            int tp = tg[l - 1], tc = tg[l];
            np += tr[tp * 33 + tc] + eb[l * 32 + tc];
        }
    }
    if (jx == 0) np += st[tg[0]] + eb[tg[0]];
#pragma unroll
    for (int o = 16; o; o >>= 1) {
        np += __shfl_xor_sync(0xffffffffu, np, o);
        ms += __shfl_xor_sync(0xffffffffu, ms, o);
    }
    const int lastidx = ms - 1;
    const float nend = en[tg[lastidx]];

    for (int l = 1; l < 512; l++) {
        float v[32];
        float mx = -1e30f;
#pragma unroll
        for (int i = 0; i < 32; i++) {
            float ai = __shfl_sync(0xffffffffu, alpha, i);
            v[i] = ai + tr[i * 33 + jx];
            mx = fmaxf(mx, v[i]);
        }
        float sa = 0.f;
#pragma unroll
        for (int i = 0; i < 32; i++) sa += __expf(v[i] - mx);
        float anew = mx + __logf(sa) + eb[l * 32 + jx];
        alpha = mk[l] ? anew : alpha;
    }
    float z = alpha + en[jx];
    float mz = z;
#pragma unroll
    for (int o = 16; o; o >>= 1) mz = fmaxf(mz, __shfl_xor_sync(0xffffffffu, mz, o));
    float sz = __expf(z - mz);
#pragma unroll
    for (int o = 16; o; o >>= 1) sz += __shfl_xor_sync(0xffffffffu, sz, o);
    float logZ = mz + __logf(sz);
    if (jx == 0) g_llh[b] = np + nend - logZ;
}

// ---------------- 5) final reduce --------------------------------------------
__global__ void final_kernel(float* out) {
    float v = g_llh[threadIdx.x];
#pragma unroll
    for (int o = 16; o; o >>= 1) v += __shfl_xor_sync(0xffffffffu, v, o);
    if (threadIdx.x == 0) out[0] = -v * (1.f / 32.f);
}

// ---------------- launch ------------------------------------------------------
extern "C" void kernel_launch(void* const* d_in, const int* in_sizes, int n_in,
                              void* d_out, int out_size) {
    const float* x     = (const float*)d_in[0];
    const int*   tags  = (const int*)d_in[1];   // int32 (JAX x64 disabled)
    const int*   mask  = (const int*)d_in[2];
    const float* wihf  = (const float*)d_in[3];
    const float* whhf  = (const float*)d_in[4];
    const float* bf    = (const float*)d_in[5];
    const float* wihb  = (const float*)d_in[6];
    const float* whhb  = (const float*)d_in[7];
    const float* bb    = (const float*)d_in[8];
    const float* lng   = (const float*)d_in[9];
    const float* lnb   = (const float*)d_in[10];
    const float* Wt    = (const float*)d_in[11];
    const float* bt    = (const float*)d_in[12];
    const float* trans = (const float*)d_in[13];
    const float* st    = (const float*)d_in[14];
    const float* en    = (const float*)d_in[15];
    float* out = (float*)d_out;

    cudaFuncSetAttribute(lstm_persist_hmma_kernel,
                         cudaFuncAttributeMaxDynamicSharedMemorySize, PERSIST_SMEM);
    cudaFuncSetAttribute(proj_hmma_kernel,
                         cudaFuncAttributeMaxDynamicSharedMemorySize, PROJ_SMEM);

    cvt_x_kernel<<<8192, 256>>>(x);
    cvt_w_kernel<<<dim3(1024, 2), 256>>>(wihf, wihb);
    cvt_wt_kernel<<<16, 256>>>(Wt);
    proj_hmma_kernel<<<dim3(16, 128, 2), 256, PROJ_SMEM>>>(bf, bb);
    lstm_persist_hmma_kernel<<<128, 512, PERSIST_SMEM>>>(whhf, whhb);
    ln_emis_kernel<<<16384, 256>>>(lng, lnb, bt);
    crf_kernel<<<32, 32>>>(tags, mask, trans, st, en);
    final_kernel<<<1, 32>>>(out);
    (void)in_sizes; (void)n_in; (void)out_size;
}